// round 9
// baseline (speedup 1.0000x reference)
#include <cuda_runtime.h>
#include <math.h>

namespace {
constexpr int Bn = 8, Cn = 4, Hn = 256, Wn = 256;
constexpr int NPIX = Bn * Hn * Wn;      // 524288
constexpr int TPB = 256;
constexpr int ROWS = 4;                 // rows per block
constexpr int NBLK = NPIX / (ROWS * TPB);  // 512
constexpr int NSLOT = 64;
}

__device__ double g_part[NSLOT];  // zero-init at load; self-reset each run
__device__ unsigned g_count;

__device__ __forceinline__ int deep_vdist(const int* __restrict__ mask, int base,
                                          int h, int w, int c, int is64) {
    int g0 = 512;
    const int lim_u = h, lim_d = Hn - 1 - h;
    const int lim = (lim_u > lim_d) ? lim_u : lim_d;
    bool done = false;
#pragma unroll 1
    for (int kb = 5; kb <= lim && !done; kb += 4) {
        int uu[4], dd[4];
#pragma unroll
        for (int j = 0; j < 4; ++j) {
            int k = kb + j;
            int hu = (k <= lim_u) ? h - k : h;
            int hd = (k <= lim_d) ? h + k : h;
            uu[j] = __ldg(mask + ((base + hu * Wn + w) << is64));
            dd[j] = __ldg(mask + ((base + hd * Wn + w) << is64));
        }
#pragma unroll
        for (int j = 0; j < 4; ++j)
            if (!done && (uu[j] != c || dd[j] != c)) { g0 = kb + j; done = true; }
    }
    return g0;
}

// Exact lower envelope on packed (cls<<20|g0^2); body runs only when m > 1.
__device__ __forceinline__ float envelope(const int* __restrict__ sp, int w,
                                          int c, float m) {
#pragma unroll 1
    for (int r = 1; r < Wn; ++r) {
        float r2 = (float)(r * r);
        if (r2 >= m) break;                  // remaining candidates >= r^2 >= m
        int xl = w - r, xr = w + r;
        if (xl < 0 && xr >= Wn) break;
        if (xl >= 0) {
            int pk = sp[xl];
            float g = ((pk >> 20) == c) ? (float)(pk & 0xFFFFF) : 0.0f;
            m = fminf(m, g + r2);
        }
        if (xr < Wn) {
            int pk = sp[xr];
            float g = ((pk >> 20) == c) ? (float)(pk & 0xFFFFF) : 0.0f;
            m = fminf(m, g + r2);
        }
    }
    return m;
}

__global__ __launch_bounds__(TPB, 4)
void boundary_loss_kernel(const float* __restrict__ pred,
                          const int* __restrict__ mask,
                          float* __restrict__ out, int out_n) {
    __shared__ int s_pk[ROWS][Wn];
    __shared__ float ws[TPB / 32];

    const int lane = threadIdx.x & 31;
    const int w = threadIdx.x;                  // TPB == Wn
    const int b = blockIdx.x >> 6;              // 64 row-quads per image
    const int hA = (blockIdx.x & 63) * ROWS;
    const int base = b * (Hn * Wn);
    const bool interior = (hA >= 4) && (hA <= Hn - ROWS - 8);  // rows hA-4..hA+11 in range

    // ---- one MLP round: is64 probe + 12-row mask window (covers 4 pixels) ----
    const int probe = __ldg(mask + 2 * lane + 1);
    int arr[12];                                // rows hA-4 .. hA+7
    if (interior) {
        const int a0 = base + (hA - 4) * Wn + w;
#pragma unroll
        for (int i = 0; i < 12; ++i) arr[i] = __ldg(mask + a0 + i * Wn);
    } else {
#pragma unroll
        for (int i = 0; i < 12; ++i) {
            int hr = hA - 4 + i;
            hr = (hr < 0) ? 0 : ((hr > Hn - 1) ? Hn - 1 : hr);
            arr[i] = __ldg(mask + base + hr * Wn + w);
        }
    }
    // int64 storage => all odd 32-bit words zero (fp prob 4^-32): reload.
    const int is64 = __all_sync(0xFFFFFFFFu, probe == 0) ? 1 : 0;
    if (is64) {
#pragma unroll
        for (int i = 0; i < 12; ++i) {
            int hr = hA - 4 + i;
            hr = (hr < 0) ? 0 : ((hr > Hn - 1) ? Hn - 1 : hr);
            arr[i] = __ldg(mask + 2 * (base + hr * Wn + w));
        }
    }

    // ---- per-pixel: class, pred load, vertical distance, publish ----
    const int ppix = b * Cn * Hn * Wn + w;
    int cls[ROWS];
    float pv[ROWS], g2[ROWS];
#pragma unroll
    for (int i = 0; i < ROWS; ++i) {
        const int c = arr[4 + i];
        cls[i] = c;
        const int h = hA + i;
        pv[i] = 0.0f;
        g2[i] = 0.0f;
        int pk = 0;
        if (c != 0) {
            pv[i] = __ldg(pred + ppix + (c * Hn + h) * Wn);
            int bits = 0;
            if (interior) {
#pragma unroll
                for (int j = 1; j <= 4; ++j)
                    bits |= ((arr[4 + i - j] != c) | (arr[4 + i + j] != c)) << (j - 1);
            } else {
#pragma unroll
                for (int j = 1; j <= 4; ++j) {
                    int uv = (j <= h) ? arr[4 + i - j] : c;
                    int dv = (h + j < Hn) ? arr[4 + i + j] : c;
                    bits |= ((uv != c) | (dv != c)) << (j - 1);
                }
            }
            int g0 = bits ? __ffs(bits) : deep_vdist(mask, base, h, w, c, is64);
            int gg = g0 * g0;
            g2[i] = (float)gg;
            pk = (c << 20) | gg;
        }
        s_pk[i][w] = pk;
    }
    __syncthreads();

    // ---- exact horizontal lower envelopes (body skipped when m == 1) ----
    const float norm = (float)(sqrt((double)(Hn * Hn + Wn * Wn)) + 1e-6);
    float term = 0.0f;
#pragma unroll
    for (int i = 0; i < ROWS; ++i) {
        if (cls[i] != 0) {
            float m = envelope(s_pk[i], w, cls[i], g2[i]);
            term += pv[i] * (sqrtf(m) / norm);
        }
    }

    // ---- block reduction + distributed accumulate + last-block finalize ----
#pragma unroll
    for (int o = 16; o > 0; o >>= 1)
        term += __shfl_down_sync(0xFFFFFFFFu, term, o);
    if (lane == 0) ws[threadIdx.x >> 5] = term;
    __syncthreads();
    if (threadIdx.x < TPB / 32) {
        float v = ws[threadIdx.x];
#pragma unroll
        for (int o = 4; o > 0; o >>= 1)
            v += __shfl_down_sync(0xFFu, v, o);
        if (threadIdx.x == 0) {
            atomicAdd(&g_part[blockIdx.x & (NSLOT - 1)], (double)v);
            __threadfence();  // order my partial add before my count bump
            unsigned prev = atomicAdd(&g_count, 1u);
            if (prev == (unsigned)(gridDim.x - 1)) {
                double total = 0.0;
#pragma unroll 1
                for (int i = 0; i < NSLOT; ++i) {
                    total += __ldcg(&g_part[i]);   // L2 read (bypass L1)
                    __stcg(&g_part[i], 0.0);       // reset for next replay
                }
                float r = (float)(total / ((double)NPIX * (Cn - 1)));
                for (int i = 0; i < out_n; ++i) out[i] = r;
                g_count = 0u;
            }
        }
    }
}

extern "C" void kernel_launch(void* const* d_in, const int* in_sizes, int n_in,
                              void* d_out, int out_size) {
    const float* pred;
    const int* mask;
    if (in_sizes[0] >= in_sizes[1]) {
        pred = (const float*)d_in[0];
        mask = (const int*)d_in[1];
    } else {
        pred = (const float*)d_in[1];
        mask = (const int*)d_in[0];
    }
    boundary_loss_kernel<<<NBLK, TPB>>>(pred, mask, (float*)d_out, out_size);
}